// round 14
// baseline (speedup 1.0000x reference)
#include <cuda_runtime.h>
#include <math.h>
#include <stdint.h>

#define NPTS 16384
#define MCTR 4096
#define NIN  64
#define NOUTF 128
#define DIMF 67
#define KNB  64
#define R2   0.25f

#define OFF_POS   (MCTR * NOUTF)
#define OFF_BATCH (OFF_POS + MCTR * 3)
#define OFF_IDX   (OFF_BATCH + MCTR)

#define SFAC 0.9999950000374996f

__device__ int g_idx[MCTR];
__device__ int g_nbr[MCTR * KNB];
__device__ int g_cnt[MCTR];

// ---------------- helpers -----------------------------------------------------

__device__ __forceinline__ uint32_t smem_u32(const void* p) {
    uint32_t a;
    asm("{ .reg .u64 t; cvta.to.shared.u64 t, %1; cvt.u32.u64 %0, t; }"
        : "=r"(a) : "l"(p));
    return a;
}
__device__ __forceinline__ uint32_t ctarank() {
    uint32_t r;
    asm("mov.u32 %0, %%cluster_ctarank;" : "=r"(r));
    return r;
}
__device__ __forceinline__ void st_cluster_u64(uint32_t local_addr, uint32_t rank,
                                               unsigned long long v) {
    asm volatile(
        "{ .reg .u32 ra; mapa.shared::cluster.u32 ra, %0, %1; "
        "st.shared::cluster.u64 [ra], %2; }"
        :: "r"(local_addr), "r"(rank), "l"(v) : "memory");
}
__device__ __forceinline__ void st_vol_smem_u64(uint32_t addr, unsigned long long v) {
    asm volatile("st.volatile.shared.u64 [%0], %1;" :: "r"(addr), "l"(v) : "memory");
}
__device__ __forceinline__ unsigned long long ld_vol_smem_u64(uint32_t addr) {
    unsigned long long v;
    asm volatile("ld.volatile.shared.u64 %0, [%1];" : "=l"(v) : "r"(addr) : "memory");
    return v;
}
__device__ __forceinline__ unsigned redux_max_u32(unsigned v) {
    unsigned r;
    asm volatile("redux.sync.max.u32 %0, %1, 0xffffffff;" : "=r"(r) : "r"(v));
    return r;
}
__device__ __forceinline__ void warp_argmax2(unsigned& v, unsigned& lo) {
    unsigned m  = redux_max_u32(v);
    unsigned cl = (v == m) ? lo : 0u;
    lo = redux_max_u32(cl);
    v  = m;
}

// ---- packed f32x2 (rn per element: bit-exact vs scalar ops) ----
__device__ __forceinline__ unsigned long long pk2(float a, float b) {
    unsigned long long r;
    asm("mov.b64 %0, {%1, %2};" : "=l"(r) : "f"(a), "f"(b));
    return r;
}
__device__ __forceinline__ void upk2(float& a, float& b, unsigned long long r) {
    asm("mov.b64 {%0, %1}, %2;" : "=f"(a), "=f"(b) : "l"(r));
}
__device__ __forceinline__ unsigned long long addx2(unsigned long long a,
                                                    unsigned long long b) {
    unsigned long long r;
    asm("add.rn.f32x2 %0, %1, %2;" : "=l"(r) : "l"(a), "l"(b));
    return r;
}
__device__ __forceinline__ unsigned long long mulx2(unsigned long long a,
                                                    unsigned long long b) {
    unsigned long long r;
    asm("mul.rn.f32x2 %0, %1, %2;" : "=l"(r) : "l"(a), "l"(b));
    return r;
}
__device__ __forceinline__ unsigned long long fma2(unsigned long long a,
                                                   unsigned long long b,
                                                   unsigned long long c) {
    unsigned long long r;
    asm("fma.rn.f32x2 %0, %1, %2, %3;" : "=l"(r) : "l"(a), "l"(b), "l"(c));
    return r;
}

// ---------------- FPS: 8 CTAs x 512 thr, tag-spin exchange (R8 exact) --------

#define FPS_CTAS 8
#define FPS_THREADS 512
#define FPS_WARPS 16
#define PPT 4

__global__ void __launch_bounds__(FPS_THREADS, 1) __cluster_dims__(FPS_CTAS, 1, 1)
fps_cluster_kernel(const float* __restrict__ pos)
{
    extern __shared__ float sm[];
    float* sx = sm;
    float* sy = sx + NPTS;
    float* sz = sy + NPTS;
    __shared__ unsigned long long s_slot[2][FPS_CTAS];
    __shared__ unsigned long long s_wkey[FPS_WARPS];

    const int t    = threadIdx.x;
    const int lane = t & 31;
    const int wid  = t >> 5;
    const uint32_t rank = ctarank();
    const int base = ((int)rank * FPS_THREADS + t) * PPT;

    for (int i = t; i < NPTS; i += FPS_THREADS) {
        sx[i] = pos[3 * i + 0];
        sy[i] = pos[3 * i + 1];
        sz[i] = pos[3 * i + 2];
    }
    if (t < 2 * FPS_CTAS) s_slot[0][t] = 0ull;
    if (t < FPS_WARPS)    s_wkey[t]    = 0ull;

    const float INF = __int_as_float(0x7f800000);
    unsigned long long px2[2], py2[2], pz2[2];
    float dmin[PPT];
#pragma unroll
    for (int j = 0; j < 2; j++) {
        int i0 = base + 2 * j, i1 = i0 + 1;
        px2[j] = pk2(pos[3 * i0 + 0], pos[3 * i1 + 0]);
        py2[j] = pk2(pos[3 * i0 + 1], pos[3 * i1 + 1]);
        pz2[j] = pk2(pos[3 * i0 + 2], pos[3 * i1 + 2]);
    }
#pragma unroll
    for (int k = 0; k < PPT; k++) dmin[k] = INF;

    __syncthreads();
    asm volatile("barrier.cluster.arrive.aligned;" ::: "memory");
    asm volatile("barrier.cluster.wait.aligned;" ::: "memory");

    float cx = sx[0], cy = sy[0], cz = sz[0];
    if (rank == 0 && t == 0) g_idx[0] = 0;

    const uint32_t slotbase = smem_u32(&s_slot[0][0]);
    const uint32_t wkeybase = smem_u32(&s_wkey[0]);

    for (int it = 1; it < MCTR; it++) {
        const unsigned tag = (unsigned)it;
        const int p = it & 1;

        unsigned long long ncx2 = pk2(-cx, -cx);
        unsigned long long ncy2 = pk2(-cy, -cy);
        unsigned long long ncz2 = pk2(-cz, -cz);
        float bvf = -1.0f;
        int   bi  = base;
#pragma unroll
        for (int j = 0; j < 2; j++) {
            unsigned long long dx2 = addx2(px2[j], ncx2);
            unsigned long long dy2 = addx2(py2[j], ncy2);
            unsigned long long dz2 = addx2(pz2[j], ncz2);
            unsigned long long s2 =
                addx2(addx2(mulx2(dx2, dx2), mulx2(dy2, dy2)), mulx2(dz2, dz2));
            float d0, d1;
            upk2(d0, d1, s2);
            float n0 = fminf(dmin[2 * j + 0], d0);
            float n1 = fminf(dmin[2 * j + 1], d1);
            dmin[2 * j + 0] = n0;
            dmin[2 * j + 1] = n1;
            if (n0 > bvf) { bvf = n0; bi = base + 2 * j; }
            if (n1 > bvf) { bvf = n1; bi = base + 2 * j + 1; }
        }
        unsigned v  = __float_as_uint(bvf);
        unsigned lo = ((16383u - (unsigned)bi) << 18) | tag;
        warp_argmax2(v, lo);

        if (lane == 0)
            st_vol_smem_u64(wkeybase + (uint32_t)wid * 8u,
                            ((unsigned long long)v << 32) | lo);

        if (wid == 0) {
            unsigned long long kk;
            for (;;) {
                kk = (lane < FPS_WARPS)
                       ? ld_vol_smem_u64(wkeybase + (uint32_t)lane * 8u) : 0ull;
                bool ok = (lane >= FPS_WARPS) || (((unsigned)kk & 0xFFFu) == tag);
                if (__all_sync(0xffffffffu, ok)) break;
            }
            unsigned gv = (unsigned)(kk >> 32), glo = (unsigned)kk;
            warp_argmax2(gv, glo);
            if (lane < FPS_CTAS) {
                unsigned long long key = ((unsigned long long)gv << 32) | glo;
                uint32_t addr = slotbase + (uint32_t)(p * FPS_CTAS + rank) * 8u;
                st_cluster_u64(addr, (uint32_t)lane, key);
            }
        }

        uint32_t a1 = slotbase + (uint32_t)(p * FPS_CTAS + (lane & 7)) * 8u;
        unsigned long long k1;
        for (;;) {
            k1 = ld_vol_smem_u64(a1);
            bool ok = (lane >= FPS_CTAS) || (((unsigned)k1 & 0xFFFu) == tag);
            if (__all_sync(0xffffffffu, ok)) break;
        }
        v  = (lane < FPS_CTAS) ? (unsigned)(k1 >> 32) : 0u;
        lo = (lane < FPS_CTAS) ? (unsigned)k1 : 0u;
        warp_argmax2(v, lo);
        int winner = (int)(16383u - ((lo >> 18) & 0x3FFFu));

        cx = sx[winner]; cy = sy[winner]; cz = sz[winner];
        if (rank == 0 && t == 0) g_idx[it] = winner;
    }
}

// ---------------- ball query (R8 exact) ---------------------------------------

#define CAND_CAP 2048

__global__ void __launch_bounds__(256) ball_kernel(const float* __restrict__ pos)
{
    __shared__ unsigned long long keys[CAND_CAP];
    __shared__ int s_cnt;

    const int m   = blockIdx.x;
    const int tid = threadIdx.x;

    if (tid == 0) s_cnt = 0;
    __syncthreads();

    int ci = g_idx[m];
    float cx = pos[ci * 3 + 0];
    float cy = pos[ci * 3 + 1];
    float cz = pos[ci * 3 + 2];

    for (int j = tid; j < NPTS; j += 256) {
        float dx = cx - pos[j * 3 + 0];
        float dy = cy - pos[j * 3 + 1];
        float dz = cz - pos[j * 3 + 2];
        float d2 = __fadd_rn(__fadd_rn(__fmul_rn(dx, dx), __fmul_rn(dy, dy)),
                             __fmul_rn(dz, dz));
        if (d2 <= R2) {
            int p = atomicAdd(&s_cnt, 1);
            if (p < CAND_CAP) {
                unsigned long long k =
                    ((unsigned long long)__float_as_uint(d2) << 32) | (unsigned)j;
                keys[p] = k;
            }
        }
    }
    __syncthreads();

    int n = s_cnt;
    if (n > CAND_CAP) n = CAND_CAP;

    if (n > KNB) {
        int npow2 = 128;
        while (npow2 < n) npow2 <<= 1;
        for (int i = n + tid; i < npow2; i += 256)
            keys[i] = 0xFFFFFFFFFFFFFFFFull;
        __syncthreads();
        for (int k2 = 2; k2 <= npow2; k2 <<= 1) {
            for (int j2 = k2 >> 1; j2 > 0; j2 >>= 1) {
                for (int i = tid; i < npow2; i += 256) {
                    int l = i ^ j2;
                    if (l > i) {
                        unsigned long long a = keys[i], b = keys[l];
                        bool up = ((i & k2) == 0);
                        if ((a > b) == up) { keys[i] = b; keys[l] = a; }
                    }
                }
                __syncthreads();
            }
        }
    }

    int cnt = n < KNB ? n : KNB;
    if (tid < cnt)
        g_nbr[m * KNB + tid] = (int)(keys[tid] & 0xFFFFFFFFull);
    if (tid == 0) g_cnt[m] = cnt;
}

// ---------------- PointConv MLP: 256 thr, 3 blocks/SM, in-place layer-1 -------
// 4 threads/row. Layer-1 computed into registers and written back IN PLACE over
// h0 (rows are warp-disjoint; __syncwarp orders read->write within the row's 4
// threads). smem ~73KB -> 3 blocks/SM (24 warps/SM vs 8 before). One thread per
// output, ascending-k accumulation: bit-identical results.

#define MTHR 256
#define W1ROW 72
#define W1SZ (67 * W1ROW)            /* 4824 */
#define W2SZ 8576
#define HROW 68

#define M_SW1  0
#define M_SW2  (M_SW1 + W1SZ)        /* 4824  */
#define M_SB1  (M_SW2 + W2SZ)        /* 13400 */
#define M_SG1  (M_SB1 + 67)
#define M_SBE1 (M_SG1 + 67)
#define M_SB2  (M_SBE1 + 67 + 3)     /* 13604, even */
#define M_SG2  (M_SB2 + 128)
#define M_SBE2 (M_SG2 + 128)
#define M_SH   (M_SBE2 + 128)        /* 13988 */
#define MLP_FLOATS (M_SH + 64 * HROW)  /* 18340 -> 73360 B */

__global__ void __launch_bounds__(MTHR) mlp_kernel(
    const float* __restrict__ x,   const float* __restrict__ pos,
    const float* __restrict__ w1,  const float* __restrict__ b1,
    const float* __restrict__ g1,  const float* __restrict__ be1,
    const float* __restrict__ w2,  const float* __restrict__ b2,
    const float* __restrict__ g2,  const float* __restrict__ be2,
    float* __restrict__ out)
{
    extern __shared__ float sm[];
    float* sw1  = sm + M_SW1;        // [67][72], zero padded cols 67..71
    float* sw2  = sm + M_SW2;        // [67][128]
    float* sb1  = sm + M_SB1;
    float* sg1  = sm + M_SG1;
    float* sbe1 = sm + M_SBE1;
    float* sb2  = sm + M_SB2;
    float* sg2  = sm + M_SG2;
    float* sbe2 = sm + M_SBE2;
    float* sh   = sm + M_SH;         // [64][68]: h0, then h1 in place
    float* sred = sm;                // [64][128] overlays sw1+sw2 after layer 2

    __shared__ int   s_nbr[KNB];
    __shared__ float s_ps[3];
    __shared__ int   s_cnt;

    const int tid = threadIdx.x;
    const int m   = blockIdx.x;

    for (int i = tid; i < W1SZ; i += MTHR) {
        int row = i / W1ROW, col = i - row * W1ROW;
        sw1[i] = (col < 67) ? w1[row * 67 + col] : 0.f;
    }
    for (int i = tid; i < W2SZ; i += MTHR) sw2[i] = w2[i];
    if (tid < 67) { sb1[tid] = b1[tid]; sg1[tid] = g1[tid]; sbe1[tid] = be1[tid]; }
    if (tid >= 128 && tid < 256) {
        int c = tid - 128;
        sb2[c] = b2[c]; sg2[c] = g2[c]; sbe2[c] = be2[c];
    }
    if (tid == 0) {
        s_cnt = g_cnt[m];
        int ci = g_idx[m];
        s_ps[0] = pos[ci*3+0]; s_ps[1] = pos[ci*3+1]; s_ps[2] = pos[ci*3+2];
    }
    __syncthreads();

    const int cnt = s_cnt;
    if (tid < cnt) s_nbr[tid] = g_nbr[m * KNB + tid];
    __syncthreads();

    for (int e = tid; e < cnt * NIN; e += MTHR) {
        int r = e >> 6, c = e & 63;
        sh[r * HROW + c] = x[s_nbr[r] * NIN + c];
    }
    for (int e = tid; e < cnt * 3; e += MTHR) {
        int r = e / 3, c = e - 3 * r;
        sh[r * HROW + 64 + c] = pos[s_nbr[r] * 3 + c] - s_ps[c];
    }
    __syncthreads();

    const int r   = tid >> 2;        // 0..63
    const int q   = tid & 3;         // 0..3
    const int c0  = q * 18;          // layer-1 cols in padded-72 space
    const int c0b = q * 32;          // layer-2 cols

    // ---- layer 1 (in place; rows valid/invalid both computed, invalid discarded
    //      downstream because sred writes & max-reduce are cnt-guarded) ----
    {
        unsigned long long acc[9];
#pragma unroll
        for (int p = 0; p < 9; p++) acc[p] = 0ull;
        for (int k = 0; k < DIMF; k++) {
            float a = sh[r * HROW + k];
            unsigned long long a2 = pk2(a, a);
            const unsigned long long* wr =
                (const unsigned long long*)&sw1[k * W1ROW + c0];
#pragma unroll
            for (int p = 0; p < 9; p++) acc[p] = fma2(a2, wr[p], acc[p]);
        }
        __syncwarp();    // all 4 row-threads finished reading this row
#pragma unroll
        for (int p = 0; p < 9; p++) {
            float f0, f1;
            upk2(f0, f1, acc[p]);
            int c = c0 + 2 * p;
            if (c < 67) {
                float v = fmaxf(f0 + sb1[c], 0.f);
                sh[r * HROW + c] = sg1[c] * (v * SFAC) + sbe1[c];
            }
            if (c + 1 < 67) {
                float v = fmaxf(f1 + sb1[c + 1], 0.f);
                sh[r * HROW + c + 1] = sg1[c + 1] * (v * SFAC) + sbe1[c + 1];
            }
        }
    }
    __syncthreads();

    // ---- layer 2 ----
    unsigned long long acc2[16];
#pragma unroll
    for (int p = 0; p < 16; p++) acc2[p] = 0ull;
    for (int k = 0; k < DIMF; k++) {
        float a = sh[r * HROW + k];
        unsigned long long a2 = pk2(a, a);
        const ulonglong2* wr = (const ulonglong2*)&sw2[k * 128 + c0b];
#pragma unroll
        for (int p = 0; p < 8; p++) {
            ulonglong2 w = wr[p];
            acc2[2*p+0] = fma2(a2, w.x, acc2[2*p+0]);
            acc2[2*p+1] = fma2(a2, w.y, acc2[2*p+1]);
        }
    }
    __syncthreads();   // weights dead; sred may overwrite sw1/sw2

    if (r < cnt) {
#pragma unroll
        for (int p = 0; p < 16; p++) {
            float f0, f1;
            upk2(f0, f1, acc2[p]);
            int c = c0b + 2 * p;
            float v0 = fmaxf(f0 + sb2[c], 0.f);
            float v1 = fmaxf(f1 + sb2[c + 1], 0.f);
            sred[r * 128 + c]     = sg2[c]     * (v0 * SFAC) + sbe2[c];
            sred[r * 128 + c + 1] = sg2[c + 1] * (v1 * SFAC) + sbe2[c + 1];
        }
    }
    __syncthreads();

    if (tid < 128) {
        int c = tid;
        float mv = sred[c];
        for (int rr = 1; rr < cnt; rr++)
            mv = fmaxf(mv, sred[rr * 128 + c]);
        out[m * NOUTF + c] = mv;
    }
}

// ---------------- epilogue (R8 exact) ------------------------------------------
__global__ void __launch_bounds__(256) epi_kernel(
    const float* __restrict__ pos, const int* __restrict__ batch,
    float* __restrict__ out)
{
    int i = blockIdx.x * 256 + threadIdx.x;
    if (i < MCTR) {
        int j = g_idx[i];
        out[OFF_POS + i * 3 + 0] = pos[j * 3 + 0];
        out[OFF_POS + i * 3 + 1] = pos[j * 3 + 1];
        out[OFF_POS + i * 3 + 2] = pos[j * 3 + 2];
        out[OFF_BATCH + i] = (float)batch[j];
        out[OFF_IDX + i]   = (float)j;
    }
}

// ---------------- launch ------------------------------------------------------
extern "C" void kernel_launch(void* const* d_in, const int* in_sizes, int n_in,
                              void* d_out, int out_size)
{
    const float* x    = (const float*)d_in[0];
    const float* pos  = (const float*)d_in[1];
    const int*   batch= (const int*)  d_in[2];
    const float* w1   = (const float*)d_in[3];
    const float* b1   = (const float*)d_in[4];
    const float* g1   = (const float*)d_in[5];
    const float* be1  = (const float*)d_in[6];
    const float* w2   = (const float*)d_in[7];
    const float* b2   = (const float*)d_in[8];
    const float* g2   = (const float*)d_in[9];
    const float* be2  = (const float*)d_in[10];
    float* out = (float*)d_out;

    cudaFuncSetAttribute(fps_cluster_kernel,
                         cudaFuncAttributeMaxDynamicSharedMemorySize,
                         3 * NPTS * (int)sizeof(float));
    cudaFuncSetAttribute(mlp_kernel, cudaFuncAttributeMaxDynamicSharedMemorySize,
                         MLP_FLOATS * (int)sizeof(float));

    fps_cluster_kernel<<<FPS_CTAS, FPS_THREADS, 3 * NPTS * sizeof(float)>>>(pos);
    ball_kernel<<<MCTR, 256>>>(pos);
    mlp_kernel<<<MCTR, MTHR, MLP_FLOATS * sizeof(float)>>>(
        x, pos, w1, b1, g1, be1, w2, b2, g2, be2, out);
    epi_kernel<<<(MCTR + 255) / 256, 256>>>(pos, batch, out);
}

// round 15
// speedup vs baseline: 1.0932x; 1.0932x over previous
#include <cuda_runtime.h>
#include <math.h>
#include <stdint.h>

#define NPTS 16384
#define MCTR 4096
#define NIN  64
#define NOUTF 128
#define DIMF 67
#define KNB  64
#define R2   0.25f

#define OFF_POS   (MCTR * NOUTF)
#define OFF_BATCH (OFF_POS + MCTR * 3)
#define OFF_IDX   (OFF_BATCH + MCTR)

#define SFAC 0.9999950000374996f

__device__ int g_idx[MCTR];
__device__ int g_nbr[MCTR * KNB];
__device__ int g_cnt[MCTR];

// ---------------- helpers -----------------------------------------------------

__device__ __forceinline__ uint32_t smem_u32(const void* p) {
    uint32_t a;
    asm("{ .reg .u64 t; cvta.to.shared.u64 t, %1; cvt.u32.u64 %0, t; }"
        : "=r"(a) : "l"(p));
    return a;
}
__device__ __forceinline__ uint32_t ctarank() {
    uint32_t r;
    asm("mov.u32 %0, %%cluster_ctarank;" : "=r"(r));
    return r;
}
__device__ __forceinline__ void st_cluster_u64(uint32_t local_addr, uint32_t rank,
                                               unsigned long long v) {
    asm volatile(
        "{ .reg .u32 ra; mapa.shared::cluster.u32 ra, %0, %1; "
        "st.shared::cluster.u64 [ra], %2; }"
        :: "r"(local_addr), "r"(rank), "l"(v) : "memory");
}
__device__ __forceinline__ void st_vol_smem_u64(uint32_t addr, unsigned long long v) {
    asm volatile("st.volatile.shared.u64 [%0], %1;" :: "r"(addr), "l"(v) : "memory");
}
__device__ __forceinline__ unsigned long long ld_vol_smem_u64(uint32_t addr) {
    unsigned long long v;
    asm volatile("ld.volatile.shared.u64 %0, [%1];" : "=l"(v) : "r"(addr) : "memory");
    return v;
}
__device__ __forceinline__ unsigned redux_max_u32(unsigned v) {
    unsigned r;
    asm volatile("redux.sync.max.u32 %0, %1, 0xffffffff;" : "=r"(r) : "r"(v));
    return r;
}
__device__ __forceinline__ void warp_argmax2(unsigned& v, unsigned& lo) {
    unsigned m  = redux_max_u32(v);
    unsigned cl = (v == m) ? lo : 0u;
    lo = redux_max_u32(cl);
    v  = m;
}

// ---- packed f32x2 (rn per element: bit-exact vs scalar ops) ----
__device__ __forceinline__ unsigned long long pk2(float a, float b) {
    unsigned long long r;
    asm("mov.b64 %0, {%1, %2};" : "=l"(r) : "f"(a), "f"(b));
    return r;
}
__device__ __forceinline__ void upk2(float& a, float& b, unsigned long long r) {
    asm("mov.b64 {%0, %1}, %2;" : "=f"(a), "=f"(b) : "l"(r));
}
__device__ __forceinline__ unsigned long long addx2(unsigned long long a,
                                                    unsigned long long b) {
    unsigned long long r;
    asm("add.rn.f32x2 %0, %1, %2;" : "=l"(r) : "l"(a), "l"(b));
    return r;
}
__device__ __forceinline__ unsigned long long mulx2(unsigned long long a,
                                                    unsigned long long b) {
    unsigned long long r;
    asm("mul.rn.f32x2 %0, %1, %2;" : "=l"(r) : "l"(a), "l"(b));
    return r;
}
__device__ __forceinline__ unsigned long long fma2(unsigned long long a,
                                                   unsigned long long b,
                                                   unsigned long long c) {
    unsigned long long r;
    asm("fma.rn.f32x2 %0, %1, %2, %3;" : "=l"(r) : "l"(a), "l"(b), "l"(c));
    return r;
}

// ---------------- FPS: 8 CTAs x 512 thr, tag-spin exchange (R8 exact) --------

#define FPS_CTAS 8
#define FPS_THREADS 512
#define FPS_WARPS 16
#define PPT 4

__global__ void __launch_bounds__(FPS_THREADS, 1) __cluster_dims__(FPS_CTAS, 1, 1)
fps_cluster_kernel(const float* __restrict__ pos)
{
    extern __shared__ float sm[];
    float* sx = sm;
    float* sy = sx + NPTS;
    float* sz = sy + NPTS;
    __shared__ unsigned long long s_slot[2][FPS_CTAS];
    __shared__ unsigned long long s_wkey[FPS_WARPS];

    const int t    = threadIdx.x;
    const int lane = t & 31;
    const int wid  = t >> 5;
    const uint32_t rank = ctarank();
    const int base = ((int)rank * FPS_THREADS + t) * PPT;

    for (int i = t; i < NPTS; i += FPS_THREADS) {
        sx[i] = pos[3 * i + 0];
        sy[i] = pos[3 * i + 1];
        sz[i] = pos[3 * i + 2];
    }
    if (t < 2 * FPS_CTAS) s_slot[0][t] = 0ull;
    if (t < FPS_WARPS)    s_wkey[t]    = 0ull;

    const float INF = __int_as_float(0x7f800000);
    unsigned long long px2[2], py2[2], pz2[2];
    float dmin[PPT];
#pragma unroll
    for (int j = 0; j < 2; j++) {
        int i0 = base + 2 * j, i1 = i0 + 1;
        px2[j] = pk2(pos[3 * i0 + 0], pos[3 * i1 + 0]);
        py2[j] = pk2(pos[3 * i0 + 1], pos[3 * i1 + 1]);
        pz2[j] = pk2(pos[3 * i0 + 2], pos[3 * i1 + 2]);
    }
#pragma unroll
    for (int k = 0; k < PPT; k++) dmin[k] = INF;

    __syncthreads();
    asm volatile("barrier.cluster.arrive.aligned;" ::: "memory");
    asm volatile("barrier.cluster.wait.aligned;" ::: "memory");

    float cx = sx[0], cy = sy[0], cz = sz[0];
    if (rank == 0 && t == 0) g_idx[0] = 0;

    const uint32_t slotbase = smem_u32(&s_slot[0][0]);
    const uint32_t wkeybase = smem_u32(&s_wkey[0]);

    for (int it = 1; it < MCTR; it++) {
        const unsigned tag = (unsigned)it;
        const int p = it & 1;

        unsigned long long ncx2 = pk2(-cx, -cx);
        unsigned long long ncy2 = pk2(-cy, -cy);
        unsigned long long ncz2 = pk2(-cz, -cz);
        float bvf = -1.0f;
        int   bi  = base;
#pragma unroll
        for (int j = 0; j < 2; j++) {
            unsigned long long dx2 = addx2(px2[j], ncx2);
            unsigned long long dy2 = addx2(py2[j], ncy2);
            unsigned long long dz2 = addx2(pz2[j], ncz2);
            unsigned long long s2 =
                addx2(addx2(mulx2(dx2, dx2), mulx2(dy2, dy2)), mulx2(dz2, dz2));
            float d0, d1;
            upk2(d0, d1, s2);
            float n0 = fminf(dmin[2 * j + 0], d0);
            float n1 = fminf(dmin[2 * j + 1], d1);
            dmin[2 * j + 0] = n0;
            dmin[2 * j + 1] = n1;
            if (n0 > bvf) { bvf = n0; bi = base + 2 * j; }
            if (n1 > bvf) { bvf = n1; bi = base + 2 * j + 1; }
        }
        unsigned v  = __float_as_uint(bvf);
        unsigned lo = ((16383u - (unsigned)bi) << 18) | tag;
        warp_argmax2(v, lo);

        if (lane == 0)
            st_vol_smem_u64(wkeybase + (uint32_t)wid * 8u,
                            ((unsigned long long)v << 32) | lo);

        if (wid == 0) {
            unsigned long long kk;
            for (;;) {
                kk = (lane < FPS_WARPS)
                       ? ld_vol_smem_u64(wkeybase + (uint32_t)lane * 8u) : 0ull;
                bool ok = (lane >= FPS_WARPS) || (((unsigned)kk & 0xFFFu) == tag);
                if (__all_sync(0xffffffffu, ok)) break;
            }
            unsigned gv = (unsigned)(kk >> 32), glo = (unsigned)kk;
            warp_argmax2(gv, glo);
            if (lane < FPS_CTAS) {
                unsigned long long key = ((unsigned long long)gv << 32) | glo;
                uint32_t addr = slotbase + (uint32_t)(p * FPS_CTAS + rank) * 8u;
                st_cluster_u64(addr, (uint32_t)lane, key);
            }
        }

        uint32_t a1 = slotbase + (uint32_t)(p * FPS_CTAS + (lane & 7)) * 8u;
        unsigned long long k1;
        for (;;) {
            k1 = ld_vol_smem_u64(a1);
            bool ok = (lane >= FPS_CTAS) || (((unsigned)k1 & 0xFFFu) == tag);
            if (__all_sync(0xffffffffu, ok)) break;
        }
        v  = (lane < FPS_CTAS) ? (unsigned)(k1 >> 32) : 0u;
        lo = (lane < FPS_CTAS) ? (unsigned)k1 : 0u;
        warp_argmax2(v, lo);
        int winner = (int)(16383u - ((lo >> 18) & 0x3FFFu));

        cx = sx[winner]; cy = sy[winner]; cz = sz[winner];
        if (rank == 0 && t == 0) g_idx[it] = winner;
    }
}

// ---------------- ball query (R8 exact) ---------------------------------------

#define CAND_CAP 2048

__global__ void __launch_bounds__(256) ball_kernel(const float* __restrict__ pos)
{
    __shared__ unsigned long long keys[CAND_CAP];
    __shared__ int s_cnt;

    const int m   = blockIdx.x;
    const int tid = threadIdx.x;

    if (tid == 0) s_cnt = 0;
    __syncthreads();

    int ci = g_idx[m];
    float cx = pos[ci * 3 + 0];
    float cy = pos[ci * 3 + 1];
    float cz = pos[ci * 3 + 2];

    for (int j = tid; j < NPTS; j += 256) {
        float dx = cx - pos[j * 3 + 0];
        float dy = cy - pos[j * 3 + 1];
        float dz = cz - pos[j * 3 + 2];
        float d2 = __fadd_rn(__fadd_rn(__fmul_rn(dx, dx), __fmul_rn(dy, dy)),
                             __fmul_rn(dz, dz));
        if (d2 <= R2) {
            int p = atomicAdd(&s_cnt, 1);
            if (p < CAND_CAP) {
                unsigned long long k =
                    ((unsigned long long)__float_as_uint(d2) << 32) | (unsigned)j;
                keys[p] = k;
            }
        }
    }
    __syncthreads();

    int n = s_cnt;
    if (n > CAND_CAP) n = CAND_CAP;

    if (n > KNB) {
        int npow2 = 128;
        while (npow2 < n) npow2 <<= 1;
        for (int i = n + tid; i < npow2; i += 256)
            keys[i] = 0xFFFFFFFFFFFFFFFFull;
        __syncthreads();
        for (int k2 = 2; k2 <= npow2; k2 <<= 1) {
            for (int j2 = k2 >> 1; j2 > 0; j2 >>= 1) {
                for (int i = tid; i < npow2; i += 256) {
                    int l = i ^ j2;
                    if (l > i) {
                        unsigned long long a = keys[i], b = keys[l];
                        bool up = ((i & k2) == 0);
                        if ((a > b) == up) { keys[i] = b; keys[l] = a; }
                    }
                }
                __syncthreads();
            }
        }
    }

    int cnt = n < KNB ? n : KNB;
    if (tid < cnt)
        g_nbr[m * KNB + tid] = (int)(keys[tid] & 0xFFFFFFFFull);
    if (tid == 0) g_cnt[m] = cnt;
}

// ---------------- PointConv MLP: R8 layout, 256 threads (4 threads/row) -------
// ONLY change vs R8: thread count. Same smem (sh0/sh1 separate, sred over sh0),
// same cnt-guards, same per-output ascending-k accumulation (bit-identical).

#define MTHR 256
#define W1ROW 72
#define W1SZ (67 * W1ROW)
#define W2SZ 8576
#define VECSZ (3*67 + 3*128)
#define HROW 68
#define SMEM_FLOATS (W1SZ + W2SZ + VECSZ + 2*64*HROW)

__global__ void __launch_bounds__(MTHR) mlp_kernel(
    const float* __restrict__ x,   const float* __restrict__ pos,
    const float* __restrict__ w1,  const float* __restrict__ b1,
    const float* __restrict__ g1,  const float* __restrict__ be1,
    const float* __restrict__ w2,  const float* __restrict__ b2,
    const float* __restrict__ g2,  const float* __restrict__ be2,
    float* __restrict__ out)
{
    extern __shared__ float sm[];
    float* sw1  = sm;                 // [67][72], zero padded cols 67..71
    float* sw2  = sw1 + W1SZ;         // [67][128]
    float* sb1  = sw2 + W2SZ;
    float* sg1  = sb1 + 67;
    float* sbe1 = sg1 + 67;
    float* sb2  = sbe1 + 67;
    float* sg2  = sb2 + 128;
    float* sbe2 = sg2 + 128;
    float* sh0  = sbe2 + 128;
    float* sh1  = sh0 + 64 * HROW;

    __shared__ int   s_nbr[KNB];
    __shared__ float s_ps[3];
    __shared__ int   s_cnt;

    const int tid = threadIdx.x;
    const int m   = blockIdx.x;

    for (int i = tid; i < W1SZ; i += MTHR) {
        int row = i / W1ROW, col = i - row * W1ROW;
        sw1[i] = (col < 67) ? w1[row * 67 + col] : 0.f;
    }
    for (int i = tid; i < W2SZ; i += MTHR) sw2[i] = w2[i];
    if (tid < 67)  { sb1[tid] = b1[tid]; sg1[tid] = g1[tid]; sbe1[tid] = be1[tid]; }
    if (tid >= 128 && tid < 256) {
        int c = tid - 128;
        sb2[c] = b2[c]; sg2[c] = g2[c]; sbe2[c] = be2[c];
    }
    if (tid == 0) {
        s_cnt = g_cnt[m];
        int ci = g_idx[m];
        s_ps[0] = pos[ci*3+0]; s_ps[1] = pos[ci*3+1]; s_ps[2] = pos[ci*3+2];
    }
    __syncthreads();

    const int cnt = s_cnt;
    if (tid < cnt) s_nbr[tid] = g_nbr[m * KNB + tid];
    __syncthreads();

    for (int e = tid; e < cnt * NIN; e += MTHR) {
        int r = e >> 6, c = e & 63;
        sh0[r * HROW + c] = x[s_nbr[r] * NIN + c];
    }
    for (int e = tid; e < cnt * 3; e += MTHR) {
        int r = e / 3, c = e - 3 * r;
        sh0[r * HROW + 64 + c] = pos[s_nbr[r] * 3 + c] - s_ps[c];
    }
    __syncthreads();

    const int r   = tid >> 2;         // 0..63
    const int q   = tid & 3;          // 0..3
    const int c0  = q * 18;           // layer-1 cols in padded-72 space
    const int c0b = q * 32;           // layer-2 cols

    // ---- layer 1 ----
    if (r < cnt) {
        unsigned long long acc[9];
#pragma unroll
        for (int p = 0; p < 9; p++) acc[p] = 0ull;
        for (int k = 0; k < DIMF; k++) {
            float a = sh0[r * HROW + k];
            unsigned long long a2 = pk2(a, a);
            const unsigned long long* wr =
                (const unsigned long long*)&sw1[k * W1ROW + c0];
#pragma unroll
            for (int p = 0; p < 9; p++) acc[p] = fma2(a2, wr[p], acc[p]);
        }
#pragma unroll
        for (int p = 0; p < 9; p++) {
            float f0, f1;
            upk2(f0, f1, acc[p]);
            int c = c0 + 2 * p;
            if (c < 67) {
                float v = fmaxf(f0 + sb1[c], 0.f);
                sh1[r * HROW + c] = sg1[c] * (v * SFAC) + sbe1[c];
            }
            if (c + 1 < 67) {
                float v = fmaxf(f1 + sb1[c + 1], 0.f);
                sh1[r * HROW + c + 1] = sg1[c + 1] * (v * SFAC) + sbe1[c + 1];
            }
        }
    }
    __syncthreads();

    // ---- layer 2 ----
    unsigned long long acc2[16];
    if (r < cnt) {
#pragma unroll
        for (int p = 0; p < 16; p++) acc2[p] = 0ull;
        for (int k = 0; k < DIMF; k++) {
            float a = sh1[r * HROW + k];
            unsigned long long a2 = pk2(a, a);
            const ulonglong2* wr = (const ulonglong2*)&sw2[k * 128 + c0b];
#pragma unroll
            for (int p = 0; p < 8; p++) {
                ulonglong2 w = wr[p];
                acc2[2*p+0] = fma2(a2, w.x, acc2[2*p+0]);
                acc2[2*p+1] = fma2(a2, w.y, acc2[2*p+1]);
            }
        }
    }
    __syncthreads();   // sh1 reads done; sred may overwrite

    float* sred = sh0;  // [64][128] overlays sh0+sh1
    if (r < cnt) {
#pragma unroll
        for (int p = 0; p < 16; p++) {
            float f0, f1;
            upk2(f0, f1, acc2[p]);
            int c = c0b + 2 * p;
            float v0 = fmaxf(f0 + sb2[c], 0.f);
            float v1 = fmaxf(f1 + sb2[c + 1], 0.f);
            sred[r * 128 + c]     = sg2[c]     * (v0 * SFAC) + sbe2[c];
            sred[r * 128 + c + 1] = sg2[c + 1] * (v1 * SFAC) + sbe2[c + 1];
        }
    }
    __syncthreads();

    if (tid < 128) {
        int c = tid;
        float mv = sred[c];
        for (int rr = 1; rr < cnt; rr++)
            mv = fmaxf(mv, sred[rr * 128 + c]);
        out[m * NOUTF + c] = mv;
    }
}

// ---------------- epilogue (R8 exact) ------------------------------------------
__global__ void __launch_bounds__(256) epi_kernel(
    const float* __restrict__ pos, const int* __restrict__ batch,
    float* __restrict__ out)
{
    int i = blockIdx.x * 256 + threadIdx.x;
    if (i < MCTR) {
        int j = g_idx[i];
        out[OFF_POS + i * 3 + 0] = pos[j * 3 + 0];
        out[OFF_POS + i * 3 + 1] = pos[j * 3 + 1];
        out[OFF_POS + i * 3 + 2] = pos[j * 3 + 2];
        out[OFF_BATCH + i] = (float)batch[j];
        out[OFF_IDX + i]   = (float)j;
    }
}

// ---------------- launch ------------------------------------------------------
extern "C" void kernel_launch(void* const* d_in, const int* in_sizes, int n_in,
                              void* d_out, int out_size)
{
    const float* x    = (const float*)d_in[0];
    const float* pos  = (const float*)d_in[1];
    const int*   batch= (const int*)  d_in[2];
    const float* w1   = (const float*)d_in[3];
    const float* b1   = (const float*)d_in[4];
    const float* g1   = (const float*)d_in[5];
    const float* be1  = (const float*)d_in[6];
    const float* w2   = (const float*)d_in[7];
    const float* b2   = (const float*)d_in[8];
    const float* g2   = (const float*)d_in[9];
    const float* be2  = (const float*)d_in[10];
    float* out = (float*)d_out;

    cudaFuncSetAttribute(fps_cluster_kernel,
                         cudaFuncAttributeMaxDynamicSharedMemorySize,
                         3 * NPTS * (int)sizeof(float));
    cudaFuncSetAttribute(mlp_kernel, cudaFuncAttributeMaxDynamicSharedMemorySize,
                         SMEM_FLOATS * (int)sizeof(float));

    fps_cluster_kernel<<<FPS_CTAS, FPS_THREADS, 3 * NPTS * sizeof(float)>>>(pos);
    ball_kernel<<<MCTR, 256>>>(pos);
    mlp_kernel<<<MCTR, MTHR, SMEM_FLOATS * sizeof(float)>>>(
        x, pos, w1, b1, g1, be1, w2, b2, g2, be2, out);
    epi_kernel<<<(MCTR + 255) / 256, 256>>>(pos, batch, out);
}

// round 16
// speedup vs baseline: 1.2995x; 1.1887x over previous
#include <cuda_runtime.h>
#include <math.h>
#include <stdint.h>

#define NPTS 16384
#define MCTR 4096
#define NIN  64
#define NOUTF 128
#define DIMF 67
#define KNB  64
#define R2   0.25f

#define OFF_POS   (MCTR * NOUTF)
#define OFF_BATCH (OFF_POS + MCTR * 3)
#define OFF_IDX   (OFF_BATCH + MCTR)

#define SFAC 0.9999950000374996f

__device__ int g_idx[MCTR];
__device__ int g_nbr[MCTR * KNB];
__device__ int g_cnt[MCTR];

// ---------------- helpers -----------------------------------------------------

__device__ __forceinline__ uint32_t smem_u32(const void* p) {
    uint32_t a;
    asm("{ .reg .u64 t; cvta.to.shared.u64 t, %1; cvt.u32.u64 %0, t; }"
        : "=r"(a) : "l"(p));
    return a;
}
__device__ __forceinline__ uint32_t ctarank() {
    uint32_t r;
    asm("mov.u32 %0, %%cluster_ctarank;" : "=r"(r));
    return r;
}
__device__ __forceinline__ void st_cluster_u64(uint32_t local_addr, uint32_t rank,
                                               unsigned long long v) {
    asm volatile(
        "{ .reg .u32 ra; mapa.shared::cluster.u32 ra, %0, %1; "
        "st.shared::cluster.u64 [ra], %2; }"
        :: "r"(local_addr), "r"(rank), "l"(v) : "memory");
}
__device__ __forceinline__ void st_vol_smem_u64(uint32_t addr, unsigned long long v) {
    asm volatile("st.volatile.shared.u64 [%0], %1;" :: "r"(addr), "l"(v) : "memory");
}
__device__ __forceinline__ unsigned long long ld_vol_smem_u64(uint32_t addr) {
    unsigned long long v;
    asm volatile("ld.volatile.shared.u64 %0, [%1];" : "=l"(v) : "r"(addr) : "memory");
    return v;
}
__device__ __forceinline__ unsigned redux_max_u32(unsigned v) {
    unsigned r;
    asm volatile("redux.sync.max.u32 %0, %1, 0xffffffff;" : "=r"(r) : "r"(v));
    return r;
}
__device__ __forceinline__ void warp_argmax2(unsigned& v, unsigned& lo) {
    unsigned m  = redux_max_u32(v);
    unsigned cl = (v == m) ? lo : 0u;
    lo = redux_max_u32(cl);
    v  = m;
}

// ---- packed f32x2 (rn per element: bit-exact vs scalar ops) ----
__device__ __forceinline__ unsigned long long pk2(float a, float b) {
    unsigned long long r;
    asm("mov.b64 %0, {%1, %2};" : "=l"(r) : "f"(a), "f"(b));
    return r;
}
__device__ __forceinline__ void upk2(float& a, float& b, unsigned long long r) {
    asm("mov.b64 {%0, %1}, %2;" : "=f"(a), "=f"(b) : "l"(r));
}
__device__ __forceinline__ unsigned long long addx2(unsigned long long a,
                                                    unsigned long long b) {
    unsigned long long r;
    asm("add.rn.f32x2 %0, %1, %2;" : "=l"(r) : "l"(a), "l"(b));
    return r;
}
__device__ __forceinline__ unsigned long long mulx2(unsigned long long a,
                                                    unsigned long long b) {
    unsigned long long r;
    asm("mul.rn.f32x2 %0, %1, %2;" : "=l"(r) : "l"(a), "l"(b));
    return r;
}
__device__ __forceinline__ unsigned long long fma2(unsigned long long a,
                                                   unsigned long long b,
                                                   unsigned long long c) {
    unsigned long long r;
    asm("fma.rn.f32x2 %0, %1, %2, %3;" : "=l"(r) : "l"(a), "l"(b), "l"(c));
    return r;
}

// ---------------- FPS: 8 CTAs x 512 thr, tag-spin exchange (R8 exact) --------

#define FPS_CTAS 8
#define FPS_THREADS 512
#define FPS_WARPS 16
#define PPT 4

__global__ void __launch_bounds__(FPS_THREADS, 1) __cluster_dims__(FPS_CTAS, 1, 1)
fps_cluster_kernel(const float* __restrict__ pos)
{
    extern __shared__ float sm[];
    float* sx = sm;
    float* sy = sx + NPTS;
    float* sz = sy + NPTS;
    __shared__ unsigned long long s_slot[2][FPS_CTAS];
    __shared__ unsigned long long s_wkey[FPS_WARPS];

    const int t    = threadIdx.x;
    const int lane = t & 31;
    const int wid  = t >> 5;
    const uint32_t rank = ctarank();
    const int base = ((int)rank * FPS_THREADS + t) * PPT;

    for (int i = t; i < NPTS; i += FPS_THREADS) {
        sx[i] = pos[3 * i + 0];
        sy[i] = pos[3 * i + 1];
        sz[i] = pos[3 * i + 2];
    }
    if (t < 2 * FPS_CTAS) s_slot[0][t] = 0ull;
    if (t < FPS_WARPS)    s_wkey[t]    = 0ull;

    const float INF = __int_as_float(0x7f800000);
    unsigned long long px2[2], py2[2], pz2[2];
    float dmin[PPT];
#pragma unroll
    for (int j = 0; j < 2; j++) {
        int i0 = base + 2 * j, i1 = i0 + 1;
        px2[j] = pk2(pos[3 * i0 + 0], pos[3 * i1 + 0]);
        py2[j] = pk2(pos[3 * i0 + 1], pos[3 * i1 + 1]);
        pz2[j] = pk2(pos[3 * i0 + 2], pos[3 * i1 + 2]);
    }
#pragma unroll
    for (int k = 0; k < PPT; k++) dmin[k] = INF;

    __syncthreads();
    asm volatile("barrier.cluster.arrive.aligned;" ::: "memory");
    asm volatile("barrier.cluster.wait.aligned;" ::: "memory");

    float cx = sx[0], cy = sy[0], cz = sz[0];
    if (rank == 0 && t == 0) g_idx[0] = 0;

    const uint32_t slotbase = smem_u32(&s_slot[0][0]);
    const uint32_t wkeybase = smem_u32(&s_wkey[0]);

    for (int it = 1; it < MCTR; it++) {
        const unsigned tag = (unsigned)it;
        const int p = it & 1;

        unsigned long long ncx2 = pk2(-cx, -cx);
        unsigned long long ncy2 = pk2(-cy, -cy);
        unsigned long long ncz2 = pk2(-cz, -cz);
        float bvf = -1.0f;
        int   bi  = base;
#pragma unroll
        for (int j = 0; j < 2; j++) {
            unsigned long long dx2 = addx2(px2[j], ncx2);
            unsigned long long dy2 = addx2(py2[j], ncy2);
            unsigned long long dz2 = addx2(pz2[j], ncz2);
            unsigned long long s2 =
                addx2(addx2(mulx2(dx2, dx2), mulx2(dy2, dy2)), mulx2(dz2, dz2));
            float d0, d1;
            upk2(d0, d1, s2);
            float n0 = fminf(dmin[2 * j + 0], d0);
            float n1 = fminf(dmin[2 * j + 1], d1);
            dmin[2 * j + 0] = n0;
            dmin[2 * j + 1] = n1;
            if (n0 > bvf) { bvf = n0; bi = base + 2 * j; }
            if (n1 > bvf) { bvf = n1; bi = base + 2 * j + 1; }
        }
        unsigned v  = __float_as_uint(bvf);
        unsigned lo = ((16383u - (unsigned)bi) << 18) | tag;
        warp_argmax2(v, lo);

        if (lane == 0)
            st_vol_smem_u64(wkeybase + (uint32_t)wid * 8u,
                            ((unsigned long long)v << 32) | lo);

        if (wid == 0) {
            unsigned long long kk;
            for (;;) {
                kk = (lane < FPS_WARPS)
                       ? ld_vol_smem_u64(wkeybase + (uint32_t)lane * 8u) : 0ull;
                bool ok = (lane >= FPS_WARPS) || (((unsigned)kk & 0xFFFu) == tag);
                if (__all_sync(0xffffffffu, ok)) break;
            }
            unsigned gv = (unsigned)(kk >> 32), glo = (unsigned)kk;
            warp_argmax2(gv, glo);
            if (lane < FPS_CTAS) {
                unsigned long long key = ((unsigned long long)gv << 32) | glo;
                uint32_t addr = slotbase + (uint32_t)(p * FPS_CTAS + rank) * 8u;
                st_cluster_u64(addr, (uint32_t)lane, key);
            }
        }

        uint32_t a1 = slotbase + (uint32_t)(p * FPS_CTAS + (lane & 7)) * 8u;
        unsigned long long k1;
        for (;;) {
            k1 = ld_vol_smem_u64(a1);
            bool ok = (lane >= FPS_CTAS) || (((unsigned)k1 & 0xFFFu) == tag);
            if (__all_sync(0xffffffffu, ok)) break;
        }
        v  = (lane < FPS_CTAS) ? (unsigned)(k1 >> 32) : 0u;
        lo = (lane < FPS_CTAS) ? (unsigned)k1 : 0u;
        warp_argmax2(v, lo);
        int winner = (int)(16383u - ((lo >> 18) & 0x3FFFu));

        cx = sx[winner]; cy = sy[winner]; cz = sz[winner];
        if (rank == 0 && t == 0) g_idx[it] = winner;
    }
}

// ---------------- ball query (R8 exact) + fused epilogue ----------------------

#define CAND_CAP 2048

__global__ void __launch_bounds__(256) ball_kernel(
    const float* __restrict__ pos, const int* __restrict__ batch,
    float* __restrict__ out)
{
    __shared__ unsigned long long keys[CAND_CAP];
    __shared__ int s_cnt;

    const int m   = blockIdx.x;
    const int tid = threadIdx.x;

    if (tid == 0) s_cnt = 0;
    __syncthreads();

    int ci = g_idx[m];
    float cx = pos[ci * 3 + 0];
    float cy = pos[ci * 3 + 1];
    float cz = pos[ci * 3 + 2];

    // fused epilogue: pos_s, batch[idx], idx (was epi_kernel)
    if (tid == 0) {
        out[OFF_POS + m * 3 + 0] = cx;
        out[OFF_POS + m * 3 + 1] = cy;
        out[OFF_POS + m * 3 + 2] = cz;
        out[OFF_BATCH + m] = (float)batch[ci];
        out[OFF_IDX + m]   = (float)ci;
    }

    for (int j = tid; j < NPTS; j += 256) {
        float dx = cx - pos[j * 3 + 0];
        float dy = cy - pos[j * 3 + 1];
        float dz = cz - pos[j * 3 + 2];
        float d2 = __fadd_rn(__fadd_rn(__fmul_rn(dx, dx), __fmul_rn(dy, dy)),
                             __fmul_rn(dz, dz));
        if (d2 <= R2) {
            int p = atomicAdd(&s_cnt, 1);
            if (p < CAND_CAP) {
                unsigned long long k =
                    ((unsigned long long)__float_as_uint(d2) << 32) | (unsigned)j;
                keys[p] = k;
            }
        }
    }
    __syncthreads();

    int n = s_cnt;
    if (n > CAND_CAP) n = CAND_CAP;

    if (n > KNB) {
        int npow2 = 128;
        while (npow2 < n) npow2 <<= 1;
        for (int i = n + tid; i < npow2; i += 256)
            keys[i] = 0xFFFFFFFFFFFFFFFFull;
        __syncthreads();
        for (int k2 = 2; k2 <= npow2; k2 <<= 1) {
            for (int j2 = k2 >> 1; j2 > 0; j2 >>= 1) {
                for (int i = tid; i < npow2; i += 256) {
                    int l = i ^ j2;
                    if (l > i) {
                        unsigned long long a = keys[i], b = keys[l];
                        bool up = ((i & k2) == 0);
                        if ((a > b) == up) { keys[i] = b; keys[l] = a; }
                    }
                }
                __syncthreads();
            }
        }
    }

    int cnt = n < KNB ? n : KNB;
    if (tid < cnt)
        g_nbr[m * KNB + tid] = (int)(keys[tid] & 0xFFFFFFFFull);
    if (tid == 0) g_cnt[m] = cnt;
}

// ---------------- PointConv MLP + max-aggregate (R8 exact) --------------------

#define W1ROW 72
#define W1SZ (67 * W1ROW)
#define W2SZ 8576
#define VECSZ (3*67 + 3*128)
#define HROW 68
#define SMEM_FLOATS (W1SZ + W2SZ + VECSZ + 2*64*HROW)

__global__ void __launch_bounds__(128) mlp_kernel(
    const float* __restrict__ x,   const float* __restrict__ pos,
    const float* __restrict__ w1,  const float* __restrict__ b1,
    const float* __restrict__ g1,  const float* __restrict__ be1,
    const float* __restrict__ w2,  const float* __restrict__ b2,
    const float* __restrict__ g2,  const float* __restrict__ be2,
    float* __restrict__ out)
{
    extern __shared__ float sm[];
    float* sw1  = sm;                 // [67][72], zero padded cols 67..71
    float* sw2  = sw1 + W1SZ;         // [67][128]
    float* sb1  = sw2 + W2SZ;
    float* sg1  = sb1 + 67;
    float* sbe1 = sg1 + 67;
    float* sb2  = sbe1 + 67;
    float* sg2  = sb2 + 128;
    float* sbe2 = sg2 + 128;
    float* sh0  = sbe2 + 128;
    float* sh1  = sh0 + 64 * HROW;

    __shared__ int   s_nbr[KNB];
    __shared__ float s_ps[3];
    __shared__ int   s_cnt;

    const int tid = threadIdx.x;
    const int m   = blockIdx.x;

    for (int i = tid; i < W1SZ; i += 128) {
        int row = i / W1ROW, col = i - row * W1ROW;
        sw1[i] = (col < 67) ? w1[row * 67 + col] : 0.f;
    }
    for (int i = tid; i < W2SZ; i += 128) sw2[i] = w2[i];
    if (tid < 67)  { sb1[tid] = b1[tid]; sg1[tid] = g1[tid]; sbe1[tid] = be1[tid]; }
    if (tid < 128) { sb2[tid] = b2[tid]; sg2[tid] = g2[tid]; sbe2[tid] = be2[tid]; }
    if (tid == 0) {
        s_cnt = g_cnt[m];
        int ci = g_idx[m];
        s_ps[0] = pos[ci*3+0]; s_ps[1] = pos[ci*3+1]; s_ps[2] = pos[ci*3+2];
    }
    __syncthreads();

    const int cnt = s_cnt;
    if (tid < cnt) s_nbr[tid] = g_nbr[m * KNB + tid];
    __syncthreads();

    for (int e = tid; e < cnt * NIN; e += 128) {
        int r = e >> 6, c = e & 63;
        sh0[r * HROW + c] = x[s_nbr[r] * NIN + c];
    }
    for (int e = tid; e < cnt * 3; e += 128) {
        int r = e / 3, c = e - 3 * r;
        sh0[r * HROW + 64 + c] = pos[s_nbr[r] * 3 + c] - s_ps[c];
    }
    __syncthreads();

    const int r    = tid >> 1;
    const int half = tid & 1;
    const int c0   = half * 36;

    if (r < cnt) {
        unsigned long long acc[18];
#pragma unroll
        for (int cc = 0; cc < 18; cc++) acc[cc] = 0ull;
        for (int i = 0; i < DIMF; i++) {
            float a = sh0[r * HROW + i];
            unsigned long long a2 = pk2(a, a);
            const ulonglong2* wr =
                reinterpret_cast<const ulonglong2*>(&sw1[i * W1ROW + c0]);
#pragma unroll
            for (int q = 0; q < 9; q++) {
                ulonglong2 w = wr[q];
                acc[2*q+0] = fma2(a2, w.x, acc[2*q+0]);
                acc[2*q+1] = fma2(a2, w.y, acc[2*q+1]);
            }
        }
#pragma unroll
        for (int cc = 0; cc < 18; cc++) {
            float f0, f1;
            upk2(f0, f1, acc[cc]);
            int c = c0 + 2 * cc;
            if (c < 67) {
                float v = f0 + sb1[c];
                v = fmaxf(v, 0.f);
                sh1[r * HROW + c] = sg1[c] * (v * SFAC) + sbe1[c];
            }
            if (c + 1 < 67) {
                float v = f1 + sb1[c + 1];
                v = fmaxf(v, 0.f);
                sh1[r * HROW + c + 1] = sg1[c + 1] * (v * SFAC) + sbe1[c + 1];
            }
        }
    }
    __syncthreads();

    unsigned long long acc2[32];
    if (r < cnt) {
#pragma unroll
        for (int cc = 0; cc < 32; cc++) acc2[cc] = 0ull;
        for (int i = 0; i < DIMF; i++) {
            float a = sh1[r * HROW + i];
            unsigned long long a2 = pk2(a, a);
            const ulonglong2* wr =
                reinterpret_cast<const ulonglong2*>(&sw2[i * 128 + half * 64]);
#pragma unroll
            for (int q = 0; q < 16; q++) {
                ulonglong2 w = wr[q];
                acc2[2*q+0] = fma2(a2, w.x, acc2[2*q+0]);
                acc2[2*q+1] = fma2(a2, w.y, acc2[2*q+1]);
            }
        }
    }
    __syncthreads();

    float* sred = sh0;
    if (r < cnt) {
#pragma unroll
        for (int cc = 0; cc < 32; cc++) {
            float f0, f1;
            upk2(f0, f1, acc2[cc]);
            int c = half * 64 + 2 * cc;
            float v0 = fmaxf(f0 + sb2[c], 0.f);
            float v1 = fmaxf(f1 + sb2[c + 1], 0.f);
            sred[r * 128 + c]     = sg2[c]     * (v0 * SFAC) + sbe2[c];
            sred[r * 128 + c + 1] = sg2[c + 1] * (v1 * SFAC) + sbe2[c + 1];
        }
    }
    __syncthreads();

    {
        int c = tid;
        float mv = sred[c];
        for (int rr = 1; rr < cnt; rr++)
            mv = fmaxf(mv, sred[rr * 128 + c]);
        out[m * NOUTF + c] = mv;
    }
}

// ---------------- launch ------------------------------------------------------
extern "C" void kernel_launch(void* const* d_in, const int* in_sizes, int n_in,
                              void* d_out, int out_size)
{
    const float* x    = (const float*)d_in[0];
    const float* pos  = (const float*)d_in[1];
    const int*   batch= (const int*)  d_in[2];
    const float* w1   = (const float*)d_in[3];
    const float* b1   = (const float*)d_in[4];
    const float* g1   = (const float*)d_in[5];
    const float* be1  = (const float*)d_in[6];
    const float* w2   = (const float*)d_in[7];
    const float* b2   = (const float*)d_in[8];
    const float* g2   = (const float*)d_in[9];
    const float* be2  = (const float*)d_in[10];
    float* out = (float*)d_out;

    cudaFuncSetAttribute(fps_cluster_kernel,
                         cudaFuncAttributeMaxDynamicSharedMemorySize,
                         3 * NPTS * (int)sizeof(float));
    cudaFuncSetAttribute(mlp_kernel, cudaFuncAttributeMaxDynamicSharedMemorySize,
                         SMEM_FLOATS * (int)sizeof(float));

    fps_cluster_kernel<<<FPS_CTAS, FPS_THREADS, 3 * NPTS * sizeof(float)>>>(pos);
    ball_kernel<<<MCTR, 256>>>(pos, batch, out);
    mlp_kernel<<<MCTR, 128, SMEM_FLOATS * sizeof(float)>>>(
        x, pos, w1, b1, g1, be1, w2, b2, g2, be2, out);
}